// round 11
// baseline (speedup 1.0000x reference)
#include <cuda_runtime.h>
#include <cstdint>

// ---------------------------------------------------------------------------
//   NF=4, NLOC=2048, NNEI=64, EMBED=128, PAIR_DIM=64, H=8, HD=16
//   force[f,l,c] = sum_n delta[n,c] * sum_h probs[h,n] * sv[nlist[n],h]
//   sv[j,h] = qn[j].Wvf[h],  Wvf[h,e] = sum_d Wforce[h*16+d]*Wv[h*16+d,e]
//   bias[h,n] = rstd_n*(Wg[h].pair[n] - mean_n*S[h]) + C[h] + mask (precomputed)
// ---------------------------------------------------------------------------

#define NROWS 8192
#define EMB   128
#define NNEI  64
#define NH    8

__device__ __align__(16) float g_q[NROWS * EMB];
__device__ __align__(16) float g_k[NROWS * EMB];
__device__ __align__(16) float g_sv[NROWS * NH];
__device__ __align__(16) float g_bias[NROWS * NH * NNEI];   // 16 MB
__device__ __align__(16) float g_wg[NH * 64];
__device__ float g_S[NH];
__device__ float g_C[NH];

// ---- packed fp32x2 helpers (SASS FFMA2, PTX-only) --------------------------
__device__ __forceinline__ unsigned long long pk2(float x, float y) {
    unsigned long long r;
    asm("mov.b64 %0, {%1, %2};" : "=l"(r) : "f"(x), "f"(y));
    return r;
}
__device__ __forceinline__ void upk2(unsigned long long v, float& x, float& y) {
    asm("mov.b64 {%0, %1}, %2;" : "=f"(x), "=f"(y) : "l"(v));
}
__device__ __forceinline__ void fma2(unsigned long long& acc,
                                     unsigned long long a, unsigned long long b) {
    asm("fma.rn.f32x2 %0, %1, %2, %0;" : "+l"(acc) : "l"(a), "l"(b));
}

#define AROWS 32

// ---------------------------------------------------------------------------
// Kernel A: LN(query) + Q/K GEMMs (f32x2) + sv + Wvf; block(0,0) also
// precomputes Wg/S/C for the bias kernel (which launches after).
// ---------------------------------------------------------------------------
__global__ __launch_bounds__(256) void lnqk_kernel(
    const float* __restrict__ query,
    const float* __restrict__ ln_g, const float* __restrict__ ln_b,
    const float* __restrict__ Wq,  const float* __restrict__ Wk,
    const float* __restrict__ Wv,  const float* __restrict__ Wf,
    const float* __restrict__ Wbias, const float* __restrict__ bbias,
    const float* __restrict__ pn_g,  const float* __restrict__ pn_b)
{
    __shared__ float qn_s[AROWS][132];
    __shared__ float Ws[128][18];
    __shared__ float wvf_s[8][132];

    const int t = threadIdx.x, w = t >> 5, l = t & 31;
    const int row0 = blockIdx.x * AROWS;
    const int m = blockIdx.y;

#pragma unroll
    for (int i = 0; i < 4; i++) {
        int r = w * 4 + i;
        float4 x = reinterpret_cast<const float4*>(query + (size_t)(row0 + r) * EMB)[l];
        float s = x.x + x.y + x.z + x.w;
#pragma unroll
        for (int o = 16; o; o >>= 1) s += __shfl_xor_sync(0xffffffffu, s, o);
        float mean = s * (1.f / 128.f);
        float d0 = x.x - mean, d1 = x.y - mean, d2 = x.z - mean, d3 = x.w - mean;
        float vs = d0 * d0 + d1 * d1 + d2 * d2 + d3 * d3;
#pragma unroll
        for (int o = 16; o; o >>= 1) vs += __shfl_xor_sync(0xffffffffu, vs, o);
        float inv = rsqrtf(vs * (1.f / 128.f) + 1e-5f);
        int e = 4 * l;
        qn_s[r][e + 0] = d0 * inv * ln_g[e + 0] + ln_b[e + 0];
        qn_s[r][e + 1] = d1 * inv * ln_g[e + 1] + ln_b[e + 1];
        qn_s[r][e + 2] = d2 * inv * ln_g[e + 2] + ln_b[e + 2];
        qn_s[r][e + 3] = d3 * inv * ln_g[e + 3] + ln_b[e + 3];
    }

    if (m == 0) {
#pragma unroll
        for (int i = 0; i < 4; i++) {
            int j = t + 256 * i;
            int h = j >> 7, e = j & 127;
            float acc = 0.f;
#pragma unroll
            for (int d = 0; d < 16; d++)
                acc += Wf[h * 16 + d] * Wv[(h * 16 + d) * EMB + e];
            wvf_s[h][e] = acc;
        }
        if (blockIdx.x == 0) {
#pragma unroll
            for (int rep = 0; rep < 2; rep++) {
                int j = t + 256 * rep;
                g_wg[j] = Wbias[j] * pn_g[j & 63];
            }
            if (t < 8) {
                float s = 0.f, c = 0.f;
#pragma unroll
                for (int p = 0; p < 64; p++) {
                    float wb = Wbias[t * 64 + p];
                    s += wb * pn_g[p];
                    c += wb * pn_b[p];
                }
                g_S[t] = s;
                g_C[t] = c + bbias[t];
            }
        }
    }
    __syncthreads();

    const float* W  = (m == 0) ? Wq : Wk;
    float* outp     = (m == 0) ? g_q : g_k;
    const int o     = t & 127;
    const int rbase = (t >> 7) * 16;

    unsigned long long acc2[16];
#pragma unroll
    for (int r = 0; r < 16; r++) acc2[r] = 0ull;

    for (int ec = 0; ec < 8; ec++) {
#pragma unroll
        for (int i = 0; i < 8; i++) {
            int flat = t + 256 * i;
            int oo = flat >> 4, ee = flat & 15;
            Ws[oo][ee] = W[oo * EMB + ec * 16 + ee];
        }
        __syncthreads();
        unsigned long long wp2[8];
        const unsigned long long* wrow =
            reinterpret_cast<const unsigned long long*>(&Ws[o][0]);
#pragma unroll
        for (int j = 0; j < 8; j++) wp2[j] = wrow[j];
#pragma unroll
        for (int r = 0; r < 16; r++) {
            const unsigned long long* qp2 =
                reinterpret_cast<const unsigned long long*>(&qn_s[rbase + r][ec * 16]);
#pragma unroll
            for (int j = 0; j < 8; j++) fma2(acc2[r], qp2[j], wp2[j]);
        }
        __syncthreads();
    }
    const float scale = (m == 0) ? 0.25f : 1.f;
#pragma unroll
    for (int r = 0; r < 16; r++) {
        float lo, hi; upk2(acc2[r], lo, hi);
        outp[(size_t)(row0 + rbase + r) * EMB + o] = (lo + hi) * scale;
    }

    if (m == 0) {
        int h = t & 7, r = t >> 3;
        const float4* qp = reinterpret_cast<const float4*>(&qn_s[r][0]);
        const float4* wp = reinterpret_cast<const float4*>(&wvf_s[h][0]);
        float a2 = 0.f;
#pragma unroll
        for (int v = 0; v < 32; v++) {
            float4 a = qp[v], bb = wp[v];
            a2 += a.x * bb.x + a.y * bb.y + a.z * bb.z + a.w * bb.w;
        }
        g_sv[(size_t)(row0 + r) * NH + h] = a2;
    }
}

// ---------------------------------------------------------------------------
// bias_kernel (DRAM-oriented): NO pair staging. Thread = (row, half):
// 8 gmem LDG.128 of its 32 dims, FFMA2 dot vs broadcast Wg, halves combined
// via shfl_xor(16). smem ~2.1 KB, 1 sync. 2 fl per block.
// ---------------------------------------------------------------------------
__global__ __launch_bounds__(256) void bias_kernel(
    const float* __restrict__ pair, const float* __restrict__ mask)
{
    __shared__ float Wg_s[512];
    __shared__ float S_s[8], C_s[8];

    const int t = threadIdx.x, w = t >> 5, l = t & 31;
    const int fl0 = blockIdx.x * 2;

    // warp w handles rows w*16 .. w*16+15; lane<16 = low dims, lane>=16 = high
    const int row = w * 16 + (l & 15);         // 0..127 within the 2-fl tile
    const int q   = l >> 4;                    // dim half

    // ---- issue pair loads immediately (8 independent LDG.128) ----
    // global pair row = fl0*64 + row   (64 rows per fl)
    const float4* prow = reinterpret_cast<const float4*>(
        pair + ((size_t)fl0 * 64 + row) * 64 + q * 32);
    float4 a[8];
#pragma unroll
    for (int v = 0; v < 8; v++) a[v] = prow[v];

    // ---- stage Wg/S/C (precomputed by lnqk block 0) ----
    Wg_s[t]       = g_wg[t];
    Wg_s[t + 256] = g_wg[t + 256];
    if (t < 8) { S_s[t] = g_S[t]; C_s[t] = g_C[t]; }
    __syncthreads();

    // ---- pack + stats ----
    unsigned long long pa[16];
#pragma unroll
    for (int v = 0; v < 8; v++) {
        pa[2 * v]     = pk2(a[v].x, a[v].y);
        pa[2 * v + 1] = pk2(a[v].z, a[v].w);
    }
    float s1 = 0.f;
#pragma unroll
    for (int v = 0; v < 8; v++) s1 += a[v].x + a[v].y + a[v].z + a[v].w;
    unsigned long long s2p = 0ull;
#pragma unroll
    for (int j = 0; j < 16; j++) fma2(s2p, pa[j], pa[j]);
    float s2lo, s2hi; upk2(s2p, s2lo, s2hi);
    float s2 = s2lo + s2hi;

    // ---- 8-head dot (Wg reads are 2-address broadcast LDS.64) ----
    float dot[8];
    {
        unsigned long long acc[8];
#pragma unroll
        for (int h = 0; h < 8; h++) acc[h] = 0ull;
#pragma unroll
        for (int j2 = 0; j2 < 8; j2++) {
#pragma unroll
            for (int h = 0; h < 8; h++) {
                const unsigned long long* wg2 =
                    reinterpret_cast<const unsigned long long*>(
                        &Wg_s[h * 64 + q * 32 + 4 * j2]);
                fma2(acc[h], pa[2 * j2],     wg2[0]);
                fma2(acc[h], pa[2 * j2 + 1], wg2[1]);
            }
        }
#pragma unroll
        for (int h = 0; h < 8; h++) {
            float lo, hi; upk2(acc[h], lo, hi);
            dot[h] = lo + hi;
        }
    }

    // ---- combine halves (partner lane l^16, same row) ----
    s1 += __shfl_xor_sync(0xffffffffu, s1, 16);
    s2 += __shfl_xor_sync(0xffffffffu, s2, 16);
#pragma unroll
    for (int h = 0; h < 8; h++)
        dot[h] += __shfl_xor_sync(0xffffffffu, dot[h], 16);

    float mean = s1 * (1.f / 64.f);
    float rstd = rsqrtf(s2 * (1.f / 64.f) - mean * mean + 1e-5f);
    float mr = mean * rstd;

    // ---- q==0 lanes write heads 0..3, q==1 lanes heads 4..7 ----
    const int fl = fl0 + (row >> 6);
    const int n = row & 63;
    const int f = fl >> 11, lrow = fl & 2047;
    float* bout = g_bias + (size_t)fl * 512;
    const int hbase = q * 4;
#pragma unroll
    for (int i = 0; i < 4; i++) {
        int h = hbase + i;
        float mval = mask[(((size_t)(f * NH + h)) * 2048 + lrow) * NNEI + n];
        bout[h * 64 + n] = rstd * dot[h] - mr * S_s[h] + C_s[h] + mval;
    }
}

// ---------------------------------------------------------------------------
// Kernel B (unchanged, 31.6 µs): gather-k logits + precomputed bias
// + softmax + force.
// ---------------------------------------------------------------------------
__global__ __launch_bounds__(256) void attn_force_kernel(
    const int* __restrict__ nlist, const float* __restrict__ delta,
    float* __restrict__ out)
{
    const int fl = blockIdx.x, f = fl >> 11;
    const int t = threadIdx.x, w = t >> 5, l = t & 31;

    __shared__ float logit[8][65];
    __shared__ float sv_s[64][9];
    __shared__ float t_s[64];

    int nq = nlist[(size_t)fl * NNEI + w * 8 + (l & 7)];
    float4 qv = reinterpret_cast<const float4*>(g_q + (size_t)fl * EMB)[l];
    const float* bb = g_bias + (size_t)fl * 512 + w * 64;
    float bk0 = bb[l], bk1 = bb[l + 32];
    float dl0 = 0.f, dl1 = 0.f;
    if (w < 3) {
        const float* dp = delta + (size_t)fl * NNEI * 3;
        dl0 = dp[l * 3 + w];
        dl1 = dp[(l + 32) * 3 + w];
    }

    {
        const float* kbase = g_k + (size_t)f * 2048 * EMB;
#pragma unroll
        for (int i = 0; i < 8; i++) {
            int nid = __shfl_sync(0xffffffffu, nq, i);
            float4 kx = reinterpret_cast<const float4*>(kbase + (size_t)nid * EMB)[l];
            float s = qv.x * kx.x + qv.y * kx.y + qv.z * kx.z + qv.w * kx.w;
            s += __shfl_xor_sync(0xffffffffu, s, 1);
            s += __shfl_xor_sync(0xffffffffu, s, 2);
            if ((l & 3) == 0) logit[l >> 2][w * 8 + i] = s;
        }
    }
    if (t < 128) {
        int n = t >> 1, half = t & 1;
        int nid = nlist[(size_t)fl * NNEI + n];
        float4 s4 = reinterpret_cast<const float4*>(
            g_sv + ((size_t)f * 2048 + nid) * NH)[half];
        sv_s[n][half * 4 + 0] = s4.x;
        sv_s[n][half * 4 + 1] = s4.y;
        sv_s[n][half * 4 + 2] = s4.z;
        sv_s[n][half * 4 + 3] = s4.w;
    }
    __syncthreads();

    {
        float v0 = logit[w][l] + bk0, v1 = logit[w][l + 32] + bk1;
        float mx = fmaxf(v0, v1);
#pragma unroll
        for (int o = 16; o; o >>= 1) mx = fmaxf(mx, __shfl_xor_sync(0xffffffffu, mx, o));
        float e0 = __expf(v0 - mx), e1 = __expf(v1 - mx);
        float ssum = e0 + e1;
#pragma unroll
        for (int o = 16; o; o >>= 1) ssum += __shfl_xor_sync(0xffffffffu, ssum, o);
        float inv = __fdividef(1.f, ssum);
        logit[w][l]      = e0 * inv;
        logit[w][l + 32] = e1 * inv;
    }
    __syncthreads();

    if (t < 64) {
        float acc = 0.f;
#pragma unroll
        for (int h = 0; h < 8; h++) acc += logit[h][t] * sv_s[t][h];
        t_s[t] = acc;
    }
    __syncthreads();

    if (w < 3) {
        float acc = dl0 * t_s[l] + dl1 * t_s[l + 32];
#pragma unroll
        for (int o = 16; o; o >>= 1) acc += __shfl_xor_sync(0xffffffffu, acc, o);
        if (l == 0) out[fl * 3 + w] = acc;
    }
}

// ---------------------------------------------------------------------------
extern "C" void kernel_launch(void* const* d_in, const int* in_sizes, int n_in,
                              void* d_out, int out_size)
{
    const float* query  = (const float*)d_in[0];
    const float* pair   = (const float*)d_in[1];
    const int*   nlist  = (const int*)d_in[2];
    const float* delta  = (const float*)d_in[3];
    const float* mask   = (const float*)d_in[4];
    const float* ln_g   = (const float*)d_in[5];
    const float* ln_b   = (const float*)d_in[6];
    const float* pn_g   = (const float*)d_in[7];
    const float* pn_b   = (const float*)d_in[8];
    const float* Wq     = (const float*)d_in[9];
    const float* Wk     = (const float*)d_in[10];
    const float* Wv     = (const float*)d_in[11];
    const float* Wbias  = (const float*)d_in[12];
    const float* bbias  = (const float*)d_in[13];
    const float* Wforce = (const float*)d_in[14];
    float* out = (float*)d_out;

    lnqk_kernel<<<dim3(NROWS / AROWS, 2), 256>>>(query, ln_g, ln_b, Wq, Wk,
                                                 Wv, Wforce, Wbias, bbias,
                                                 pn_g, pn_b);
    bias_kernel<<<NROWS / 2, 256>>>(pair, mask);
    attn_force_kernel<<<NROWS, 256>>>(nlist, delta, out);
}